// round 13
// baseline (speedup 1.0000x reference)
#include <cuda_runtime.h>
#include <cuda_fp16.h>
#include <stdint.h>

// Problem constants
#define TT   16384          // tokens = B*S
#define DD   1024           // model dim
#define EE   8              // experts
#define HH   2752           // ffn hidden
#define HP   2816           // hidden padded to multiple of 128
#define MMAX 33792          // 264*128 >= 32768 + 8*127 worst-case padded rows
#define MT_MAX 264

// -------------------- device scratch (no cudaMalloc allowed) --------------------
__device__ __half g_xg [(size_t)MMAX * DD];       // gathered tokens, fp16, segmented
__device__ __half g_w1h[(size_t)EE * HP * DD];    // w1 fp16 [e][HP][D], pad rows zero
__device__ __half g_w3h[(size_t)EE * HP * DD];    // w3 fp16
__device__ __half g_w2h[(size_t)EE * DD * HP];    // w2 fp16 [e][D][HP], pad cols zero
__device__ __half g_t3 [(size_t)MMAX * HP];       // X @ W3^T
__device__ __half g_h  [(size_t)MMAX * HP];       // silu(X@W1^T) * t3
__device__ float  g_yrows[(size_t)MMAX * DD];     // per-row FFN output (fp32)
__device__ int    g_eids [TT * 2];
__device__ float  g_gws  [TT * 2];
__device__ int    g_rowof[TT * 2];
__device__ int    g_perm [MMAX];
__device__ int    g_counts[EE];
__device__ int    g_cursor[EE];
__device__ int    g_segstart[EE + 1];
__device__ int    g_mtile_e[MT_MAX];
__device__ int    g_nmtiles;

// -------------------- asm helpers --------------------
__device__ __forceinline__ void ldsm4(uint32_t* r, uint32_t a) {
    asm volatile("ldmatrix.sync.aligned.m8n8.x4.shared.b16 {%0,%1,%2,%3}, [%4];"
                 : "=r"(r[0]), "=r"(r[1]), "=r"(r[2]), "=r"(r[3]) : "r"(a));
}
__device__ __forceinline__ void ldsm2(uint32_t* r, uint32_t a) {
    asm volatile("ldmatrix.sync.aligned.m8n8.x2.shared.b16 {%0,%1}, [%2];"
                 : "=r"(r[0]), "=r"(r[1]) : "r"(a));
}
__device__ __forceinline__ void mma16816(float* c, const uint32_t* a, uint32_t b0, uint32_t b1) {
    asm volatile("mma.sync.aligned.m16n8k16.row.col.f32.f16.f16.f32 "
                 "{%0,%1,%2,%3}, {%4,%5,%6,%7}, {%8,%9}, {%0,%1,%2,%3};"
                 : "+f"(c[0]), "+f"(c[1]), "+f"(c[2]), "+f"(c[3])
                 : "r"(a[0]), "r"(a[1]), "r"(a[2]), "r"(a[3]), "r"(b0), "r"(b1));
}
__device__ __forceinline__ void cp16(uint32_t s, const void* g) {
    asm volatile("cp.async.cg.shared.global [%0], [%1], 16;" :: "r"(s), "l"(g));
}

// -------------------- routing --------------------
__global__ void moe_init() { if (threadIdx.x < EE) g_counts[threadIdx.x] = 0; }

__global__ void __launch_bounds__(256) moe_router(const float* __restrict__ x,
                                                  const float* __restrict__ gw) {
    __shared__ float sgw[EE * DD];
    for (int i = threadIdx.x; i < EE * DD; i += 256) sgw[i] = gw[i];
    __syncthreads();
    const int t    = blockIdx.x * 8 + (threadIdx.x >> 5);
    const int lane = threadIdx.x & 31;
    const float* xr = x + (size_t)t * DD;
    float acc[EE];
    #pragma unroll
    for (int e = 0; e < EE; e++) acc[e] = 0.f;
    for (int d = lane; d < DD; d += 32) {
        float xv = xr[d];
        #pragma unroll
        for (int e = 0; e < EE; e++) acc[e] += xv * sgw[e * DD + d];
    }
    #pragma unroll
    for (int e = 0; e < EE; e++) {
        #pragma unroll
        for (int o = 16; o > 0; o >>= 1) acc[e] += __shfl_xor_sync(0xffffffffu, acc[e], o);
    }
    if (lane == 0) {
        float m = acc[0];
        #pragma unroll
        for (int e = 1; e < EE; e++) m = fmaxf(m, acc[e]);
        float p[EE];
        #pragma unroll
        for (int e = 0; e < EE; e++) p[e] = __expf(acc[e] - m);
        int i0 = 0; float b0 = p[0];
        #pragma unroll
        for (int e = 1; e < EE; e++) if (p[e] > b0) { b0 = p[e]; i0 = e; }  // ties -> lower idx
        int i1 = (i0 == 0) ? 1 : 0; float b1 = p[i1];
        #pragma unroll
        for (int e = 0; e < EE; e++) if (e != i0 && p[e] > b1) { b1 = p[e]; i1 = e; }
        // softmax denom cancels in top-2 renormalization
        float inv = 1.f / (b0 + b1);
        g_eids[2*t]   = i0;       g_eids[2*t+1] = i1;
        g_gws [2*t]   = b0 * inv; g_gws [2*t+1] = b1 * inv;
        atomicAdd(&g_counts[i0], 1);
        atomicAdd(&g_counts[i1], 1);
    }
}

__global__ void moe_segplan() {
    int off = 0;
    for (int e = 0; e < EE; e++) {
        g_segstart[e] = off;
        g_cursor[e]   = 0;
        int mt = (g_counts[e] + 127) >> 7;
        for (int i = 0; i < mt; i++) g_mtile_e[(off >> 7) + i] = e;
        off += mt << 7;
    }
    g_segstart[EE] = off;
    g_nmtiles = off >> 7;
}

__global__ void __launch_bounds__(256) moe_build_perm() {
    int t = blockIdx.x * 256 + threadIdx.x;
    #pragma unroll
    for (int k = 0; k < 2; k++) {
        int e   = g_eids[2*t + k];
        int pos = atomicAdd(&g_cursor[e], 1);
        int row = g_segstart[e] + pos;
        g_perm[row]     = t;
        g_rowof[2*t+k]  = row;
    }
}

// gather tokens into segmented fp16 layout; pad rows zeroed
__global__ void __launch_bounds__(256) moe_gather(const float* __restrict__ x) {
    const int r = blockIdx.x;
    int e = 0;
    #pragma unroll
    for (int q = 0; q < EE - 1; q++) if (r >= g_segstart[q + 1]) e = q + 1;
    const bool valid = (r - g_segstart[e]) < g_counts[e];
    const int i = threadIdx.x * 4;
    float4 v = make_float4(0.f, 0.f, 0.f, 0.f);
    if (valid) {
        int t = g_perm[r];
        v = *(const float4*)(x + (size_t)t * DD + i);
    }
    __half2* dst = (__half2*)(g_xg + (size_t)r * DD + i);
    dst[0] = __floats2half2_rn(v.x, v.y);
    dst[1] = __floats2half2_rn(v.z, v.w);
}

// -------------------- weight conversion fp32 -> fp16 (padded) --------------------
__global__ void __launch_bounds__(256) moe_conv_w13(const float* __restrict__ w1,
                                                    const float* __restrict__ w3) {
    size_t i = (size_t)blockIdx.x * 256 + threadIdx.x;   // over EE*HP*DD
    int d = (int)(i & (DD - 1));
    size_t rem = i >> 10;
    int r = (int)(rem % HP);
    int e = (int)(rem / HP);
    __half v1 = __float2half_rn(0.f), v3 = __float2half_rn(0.f);
    if (r < HH) {
        size_t src = ((size_t)e * HH + r) * DD + d;
        v1 = __float2half_rn(w1[src]);
        v3 = __float2half_rn(w3[src]);
    }
    g_w1h[i] = v1; g_w3h[i] = v3;
}

__global__ void __launch_bounds__(256) moe_conv_w2(const float* __restrict__ w2) {
    size_t i = (size_t)blockIdx.x * 256 + threadIdx.x;   // over EE*DD*HP
    int c = (int)(i % HP);
    size_t rem = i / HP;
    int r = (int)(rem & (DD - 1));
    int e = (int)(rem >> 10);
    __half v = __float2half_rn(0.f);
    if (c < HH) v = __float2half_rn(w2[((size_t)e * DD + r) * HH + c]);
    g_w2h[i] = v;
}

// -------------------- GEMM: C[128x128] = A[128xK] @ B[128xK]^T --------------------
// MODE 0: A=g_xg  B=g_w3h -> g_t3 (fp16)
// MODE 1: A=g_xg  B=g_w1h -> g_h = silu(acc) * g_t3 (fp16)
// MODE 2: A=g_h   B=g_w2h -> g_yrows (fp32)
template<int MODE>
__global__ void __launch_bounds__(256) moe_gemm() {
    constexpr int K   = (MODE == 2) ? HP : DD;
    constexpr int KIT = K / 64;

    const int mt = blockIdx.y;
    if (mt >= g_nmtiles) return;
    const int e = g_mtile_e[mt];

    const __half* A = (MODE == 2) ? g_h : g_xg;
    const __half* B = (MODE == 0) ? g_w3h + (size_t)e * HP * DD :
                      (MODE == 1) ? g_w1h + (size_t)e * HP * DD :
                                    g_w2h + (size_t)e * DD * HP;

    extern __shared__ char smem_raw[];
    const uint32_t sbase = (uint32_t)__cvta_generic_to_shared(smem_raw);
    const uint32_t sA = sbase, sB = sbase + 3 * 16384;
    const int tid = threadIdx.x;
    const __half* Ag = A + (size_t)mt * 128 * K;
    const __half* Bg = B + (size_t)blockIdx.x * 128 * K;

    auto load_stage = [&](int st, int kt) {
        uint32_t da = sA + st * 16384, db = sB + st * 16384;
        const __half* ga = Ag + kt * 64;
        const __half* gb = Bg + kt * 64;
        #pragma unroll
        for (int i = 0; i < 4; i++) {
            int idx = i * 256 + tid;          // 1024 chunks of 16B = 128 rows x 8 chunks
            int r = idx >> 3, c = idx & 7;
            uint32_t so = (uint32_t)(r * 128) + (uint32_t)((c ^ (r & 7)) << 4);
            size_t go = (size_t)r * K + c * 8;
            cp16(da + so, ga + go);
            cp16(db + so, gb + go);
        }
    };
    load_stage(0, 0); asm volatile("cp.async.commit_group;" ::: "memory");
    load_stage(1, 1); asm volatile("cp.async.commit_group;" ::: "memory");

    const int lane = tid & 31, wid = tid >> 5;
    const int wm = (wid >> 2) * 64, wn = (wid & 3) * 32;

    float acc[4][4][4];
    #pragma unroll
    for (int a = 0; a < 4; a++)
        #pragma unroll
        for (int b = 0; b < 4; b++)
            #pragma unroll
            for (int q = 0; q < 4; q++) acc[a][b][q] = 0.f;

    #pragma unroll 1
    for (int kt = 0; kt < KIT; kt++) {
        asm volatile("cp.async.wait_group 1;" ::: "memory");
        __syncthreads();
        if (kt + 2 < KIT) load_stage((kt + 2) % 3, kt + 2);
        asm volatile("cp.async.commit_group;" ::: "memory");
        const uint32_t a_s = sA + (kt % 3) * 16384;
        const uint32_t b_s = sB + (kt % 3) * 16384;
        #pragma unroll
        for (int kk = 0; kk < 4; kk++) {
            uint32_t af[4][4], bf[4][2];
            #pragma unroll
            for (int mb = 0; mb < 4; mb++) {
                int r  = wm + mb * 16 + (lane & 15);
                int cb = kk * 2 + (lane >> 4);          // 16B-chunk index within 8
                ldsm4(af[mb], a_s + (uint32_t)(r * 128) + (uint32_t)((cb ^ (r & 7)) << 4));
            }
            #pragma unroll
            for (int nb = 0; nb < 4; nb++) {
                int l15 = lane & 15;
                int r   = wn + nb * 8 + (l15 & 7);
                int cb  = kk * 2 + (l15 >> 3);
                ldsm2(bf[nb], b_s + (uint32_t)(r * 128) + (uint32_t)((cb ^ (r & 7)) << 4));
            }
            #pragma unroll
            for (int mb = 0; mb < 4; mb++)
                #pragma unroll
                for (int nb = 0; nb < 4; nb++)
                    mma16816(acc[mb][nb], af[mb], bf[nb][0], bf[nb][1]);
        }
    }

    // epilogue
    const int row0 = mt * 128 + wm;
    const int col0 = blockIdx.x * 128 + wn;
    #pragma unroll
    for (int mb = 0; mb < 4; mb++) {
        #pragma unroll
        for (int nb = 0; nb < 4; nb++) {
            int r = row0 + mb * 16 + (lane >> 2);
            int c = col0 + nb * 8 + (lane & 3) * 2;
            float* a = acc[mb][nb];
            if (MODE == 0) {
                *(__half2*)(g_t3 + (size_t)r       * HP + c) = __floats2half2_rn(a[0], a[1]);
                *(__half2*)(g_t3 + (size_t)(r + 8) * HP + c) = __floats2half2_rn(a[2], a[3]);
            } else if (MODE == 1) {
                float2 t0 = __half22float2(*(__half2*)(g_t3 + (size_t)r       * HP + c));
                float2 t1 = __half22float2(*(__half2*)(g_t3 + (size_t)(r + 8) * HP + c));
                float s0 = a[0] / (1.f + __expf(-a[0]));
                float s1 = a[1] / (1.f + __expf(-a[1]));
                float s2 = a[2] / (1.f + __expf(-a[2]));
                float s3 = a[3] / (1.f + __expf(-a[3]));
                *(__half2*)(g_h + (size_t)r       * HP + c) = __floats2half2_rn(s0 * t0.x, s1 * t0.y);
                *(__half2*)(g_h + (size_t)(r + 8) * HP + c) = __floats2half2_rn(s2 * t1.x, s3 * t1.y);
            } else {
                *(float2*)(g_yrows + (size_t)r       * DD + c) = make_float2(a[0], a[1]);
                *(float2*)(g_yrows + (size_t)(r + 8) * DD + c) = make_float2(a[2], a[3]);
            }
        }
    }
}

// -------------------- combine (deterministic gather) --------------------
__global__ void __launch_bounds__(256) moe_combine(float* __restrict__ out) {
    const int t = blockIdx.x;
    const int i = threadIdx.x * 4;
    int   r0 = g_rowof[2*t],  r1 = g_rowof[2*t+1];
    float w0 = g_gws [2*t],  w1 = g_gws [2*t+1];
    float4 a = *(const float4*)(g_yrows + (size_t)r0 * DD + i);
    float4 b = *(const float4*)(g_yrows + (size_t)r1 * DD + i);
    float4 o;
    o.x = w0 * a.x + w1 * b.x;
    o.y = w0 * a.y + w1 * b.y;
    o.z = w0 * a.z + w1 * b.z;
    o.w = w0 * a.w + w1 * b.w;
    *(float4*)(out + (size_t)t * DD + i) = o;
}

// -------------------- launch --------------------
extern "C" void kernel_launch(void* const* d_in, const int* in_sizes, int n_in,
                              void* d_out, int out_size) {
    (void)in_sizes; (void)n_in; (void)out_size;
    const float* x  = (const float*)d_in[0];
    const float* gw = (const float*)d_in[1];
    const float* w1 = (const float*)d_in[2];
    const float* w2 = (const float*)d_in[3];
    const float* w3 = (const float*)d_in[4];
    float* out = (float*)d_out;

    const int smem = 3 * 2 * 16384;  // 96 KB: 3 stages x (16KB A + 16KB B)
    cudaFuncSetAttribute(moe_gemm<0>, cudaFuncAttributeMaxDynamicSharedMemorySize, smem);
    cudaFuncSetAttribute(moe_gemm<1>, cudaFuncAttributeMaxDynamicSharedMemorySize, smem);
    cudaFuncSetAttribute(moe_gemm<2>, cudaFuncAttributeMaxDynamicSharedMemorySize, smem);

    moe_init<<<1, 32>>>();
    moe_router<<<TT / 8, 256>>>(x, gw);
    moe_segplan<<<1, 1>>>();
    moe_build_perm<<<TT / 256, 256>>>();
    moe_gather<<<MMAX, 256>>>(x);
    moe_conv_w13<<<(EE * HP * DD) / 256, 256>>>(w1, w3);
    moe_conv_w2 <<<(EE * DD * HP) / 256, 256>>>(w2);

    moe_gemm<0><<<dim3(HP / 128, MT_MAX), 256, smem>>>();
    moe_gemm<1><<<dim3(HP / 128, MT_MAX), 256, smem>>>();
    moe_gemm<2><<<dim3(DD / 128, MT_MAX), 256, smem>>>();

    moe_combine<<<TT, 256>>>(out);
}

// round 14
// speedup vs baseline: 1.0005x; 1.0005x over previous
#include <cuda_runtime.h>
#include <cuda_fp16.h>
#include <stdint.h>

// Problem constants
#define TT   16384          // tokens = B*S
#define DD   1024           // model dim
#define EE   8              // experts
#define HH   2752           // ffn hidden
#define HP   2816           // hidden padded to multiple of 128
#define MMAX 33792          // 264*128 >= 32768 + 8*127 worst-case padded rows
#define MT_MAX 264

// -------------------- device scratch (no cudaMalloc allowed) --------------------
__device__ __half g_xg [(size_t)MMAX * DD];       // gathered tokens, fp16, segmented
__device__ __half g_w1h[(size_t)EE * HP * DD];    // w1 fp16 [e][HP][D], pad rows zero
__device__ __half g_w3h[(size_t)EE * HP * DD];    // w3 fp16
__device__ __half g_w2h[(size_t)EE * DD * HP];    // w2 fp16 [e][D][HP], pad cols zero
__device__ __half g_t3 [(size_t)MMAX * HP];       // X @ W3^T
__device__ __half g_h  [(size_t)MMAX * HP];       // silu(X@W1^T) * t3
__device__ float  g_yrows[(size_t)MMAX * DD];     // per-row FFN output (fp32)
__device__ int    g_eids [TT * 2];
__device__ float  g_gws  [TT * 2];
__device__ int    g_rowof[TT * 2];
__device__ int    g_perm [MMAX];
__device__ int    g_counts[EE];
__device__ int    g_cursor[EE];
__device__ int    g_segstart[EE + 1];
__device__ int    g_mtile_e[MT_MAX];
__device__ int    g_nmtiles;

// -------------------- asm helpers --------------------
__device__ __forceinline__ void ldsm4(uint32_t* r, uint32_t a) {
    asm volatile("ldmatrix.sync.aligned.m8n8.x4.shared.b16 {%0,%1,%2,%3}, [%4];"
                 : "=r"(r[0]), "=r"(r[1]), "=r"(r[2]), "=r"(r[3]) : "r"(a));
}
__device__ __forceinline__ void ldsm2(uint32_t* r, uint32_t a) {
    asm volatile("ldmatrix.sync.aligned.m8n8.x2.shared.b16 {%0,%1}, [%2];"
                 : "=r"(r[0]), "=r"(r[1]) : "r"(a));
}
__device__ __forceinline__ void mma16816(float* c, const uint32_t* a, uint32_t b0, uint32_t b1) {
    asm volatile("mma.sync.aligned.m16n8k16.row.col.f32.f16.f16.f32 "
                 "{%0,%1,%2,%3}, {%4,%5,%6,%7}, {%8,%9}, {%0,%1,%2,%3};"
                 : "+f"(c[0]), "+f"(c[1]), "+f"(c[2]), "+f"(c[3])
                 : "r"(a[0]), "r"(a[1]), "r"(a[2]), "r"(a[3]), "r"(b0), "r"(b1));
}
__device__ __forceinline__ void cp16(uint32_t s, const void* g) {
    asm volatile("cp.async.cg.shared.global [%0], [%1], 16;" :: "r"(s), "l"(g));
}

// -------------------- routing --------------------
__global__ void moe_init() { if (threadIdx.x < EE) g_counts[threadIdx.x] = 0; }

__global__ void __launch_bounds__(256) moe_router(const float* __restrict__ x,
                                                  const float* __restrict__ gw) {
    __shared__ float sgw[EE * DD];
    for (int i = threadIdx.x; i < EE * DD; i += 256) sgw[i] = gw[i];
    __syncthreads();
    const int t    = blockIdx.x * 8 + (threadIdx.x >> 5);
    const int lane = threadIdx.x & 31;
    const float* xr = x + (size_t)t * DD;
    float acc[EE];
    #pragma unroll
    for (int e = 0; e < EE; e++) acc[e] = 0.f;
    for (int d = lane; d < DD; d += 32) {
        float xv = xr[d];
        #pragma unroll
        for (int e = 0; e < EE; e++) acc[e] += xv * sgw[e * DD + d];
    }
    #pragma unroll
    for (int e = 0; e < EE; e++) {
        #pragma unroll
        for (int o = 16; o > 0; o >>= 1) acc[e] += __shfl_xor_sync(0xffffffffu, acc[e], o);
    }
    if (lane == 0) {
        float m = acc[0];
        #pragma unroll
        for (int e = 1; e < EE; e++) m = fmaxf(m, acc[e]);
        float p[EE];
        #pragma unroll
        for (int e = 0; e < EE; e++) p[e] = __expf(acc[e] - m);
        int i0 = 0; float b0 = p[0];
        #pragma unroll
        for (int e = 1; e < EE; e++) if (p[e] > b0) { b0 = p[e]; i0 = e; }  // ties -> lower idx
        int i1 = (i0 == 0) ? 1 : 0; float b1 = p[i1];
        #pragma unroll
        for (int e = 0; e < EE; e++) if (e != i0 && p[e] > b1) { b1 = p[e]; i1 = e; }
        // softmax denom cancels in top-2 renormalization
        float inv = 1.f / (b0 + b1);
        g_eids[2*t]   = i0;       g_eids[2*t+1] = i1;
        g_gws [2*t]   = b0 * inv; g_gws [2*t+1] = b1 * inv;
        atomicAdd(&g_counts[i0], 1);
        atomicAdd(&g_counts[i1], 1);
    }
}

__global__ void moe_segplan() {
    int off = 0;
    for (int e = 0; e < EE; e++) {
        g_segstart[e] = off;
        g_cursor[e]   = 0;
        int mt = (g_counts[e] + 127) >> 7;
        for (int i = 0; i < mt; i++) g_mtile_e[(off >> 7) + i] = e;
        off += mt << 7;
    }
    g_segstart[EE] = off;
    g_nmtiles = off >> 7;
}

__global__ void __launch_bounds__(256) moe_build_perm() {
    int t = blockIdx.x * 256 + threadIdx.x;
    #pragma unroll
    for (int k = 0; k < 2; k++) {
        int e   = g_eids[2*t + k];
        int pos = atomicAdd(&g_cursor[e], 1);
        int row = g_segstart[e] + pos;
        g_perm[row]     = t;
        g_rowof[2*t+k]  = row;
    }
}

// gather tokens into segmented fp16 layout; pad rows zeroed
__global__ void __launch_bounds__(256) moe_gather(const float* __restrict__ x) {
    const int r = blockIdx.x;
    int e = 0;
    #pragma unroll
    for (int q = 0; q < EE - 1; q++) if (r >= g_segstart[q + 1]) e = q + 1;
    const bool valid = (r - g_segstart[e]) < g_counts[e];
    const int i = threadIdx.x * 4;
    float4 v = make_float4(0.f, 0.f, 0.f, 0.f);
    if (valid) {
        int t = g_perm[r];
        v = *(const float4*)(x + (size_t)t * DD + i);
    }
    __half2* dst = (__half2*)(g_xg + (size_t)r * DD + i);
    dst[0] = __floats2half2_rn(v.x, v.y);
    dst[1] = __floats2half2_rn(v.z, v.w);
}

// -------------------- weight conversion fp32 -> fp16 (padded) --------------------
__global__ void __launch_bounds__(256) moe_conv_w13(const float* __restrict__ w1,
                                                    const float* __restrict__ w3) {
    size_t i = (size_t)blockIdx.x * 256 + threadIdx.x;   // over EE*HP*DD
    int d = (int)(i & (DD - 1));
    size_t rem = i >> 10;
    int r = (int)(rem % HP);
    int e = (int)(rem / HP);
    __half v1 = __float2half_rn(0.f), v3 = __float2half_rn(0.f);
    if (r < HH) {
        size_t src = ((size_t)e * HH + r) * DD + d;
        v1 = __float2half_rn(w1[src]);
        v3 = __float2half_rn(w3[src]);
    }
    g_w1h[i] = v1; g_w3h[i] = v3;
}

__global__ void __launch_bounds__(256) moe_conv_w2(const float* __restrict__ w2) {
    size_t i = (size_t)blockIdx.x * 256 + threadIdx.x;   // over EE*DD*HP
    int c = (int)(i % HP);
    size_t rem = i / HP;
    int r = (int)(rem & (DD - 1));
    int e = (int)(rem >> 10);
    __half v = __float2half_rn(0.f);
    if (c < HH) v = __float2half_rn(w2[((size_t)e * DD + r) * HH + c]);
    g_w2h[i] = v;
}

// -------------------- GEMM: C[128x128] = A[128xK] @ B[128xK]^T --------------------
// MODE 0: A=g_xg  B=g_w3h -> g_t3 (fp16)
// MODE 1: A=g_xg  B=g_w1h -> g_h = silu(acc) * g_t3 (fp16)
// MODE 2: A=g_h   B=g_w2h -> g_yrows (fp32)
template<int MODE>
__global__ void __launch_bounds__(256) moe_gemm() {
    constexpr int K   = (MODE == 2) ? HP : DD;
    constexpr int KIT = K / 64;

    const int mt = blockIdx.y;
    if (mt >= g_nmtiles) return;
    const int e = g_mtile_e[mt];

    const __half* A = (MODE == 2) ? g_h : g_xg;
    const __half* B = (MODE == 0) ? g_w3h + (size_t)e * HP * DD :
                      (MODE == 1) ? g_w1h + (size_t)e * HP * DD :
                                    g_w2h + (size_t)e * DD * HP;

    extern __shared__ char smem_raw[];
    const uint32_t sbase = (uint32_t)__cvta_generic_to_shared(smem_raw);
    const uint32_t sA = sbase, sB = sbase + 3 * 16384;
    const int tid = threadIdx.x;
    const __half* Ag = A + (size_t)mt * 128 * K;
    const __half* Bg = B + (size_t)blockIdx.x * 128 * K;

    auto load_stage = [&](int st, int kt) {
        uint32_t da = sA + st * 16384, db = sB + st * 16384;
        const __half* ga = Ag + kt * 64;
        const __half* gb = Bg + kt * 64;
        #pragma unroll
        for (int i = 0; i < 4; i++) {
            int idx = i * 256 + tid;          // 1024 chunks of 16B = 128 rows x 8 chunks
            int r = idx >> 3, c = idx & 7;
            uint32_t so = (uint32_t)(r * 128) + (uint32_t)((c ^ (r & 7)) << 4);
            size_t go = (size_t)r * K + c * 8;
            cp16(da + so, ga + go);
            cp16(db + so, gb + go);
        }
    };
    load_stage(0, 0); asm volatile("cp.async.commit_group;" ::: "memory");
    load_stage(1, 1); asm volatile("cp.async.commit_group;" ::: "memory");

    const int lane = tid & 31, wid = tid >> 5;
    const int wm = (wid >> 2) * 64, wn = (wid & 3) * 32;

    float acc[4][4][4];
    #pragma unroll
    for (int a = 0; a < 4; a++)
        #pragma unroll
        for (int b = 0; b < 4; b++)
            #pragma unroll
            for (int q = 0; q < 4; q++) acc[a][b][q] = 0.f;

    #pragma unroll 1
    for (int kt = 0; kt < KIT; kt++) {
        asm volatile("cp.async.wait_group 1;" ::: "memory");
        __syncthreads();
        if (kt + 2 < KIT) load_stage((kt + 2) % 3, kt + 2);
        asm volatile("cp.async.commit_group;" ::: "memory");
        const uint32_t a_s = sA + (kt % 3) * 16384;
        const uint32_t b_s = sB + (kt % 3) * 16384;
        #pragma unroll
        for (int kk = 0; kk < 4; kk++) {
            uint32_t af[4][4], bf[4][2];
            #pragma unroll
            for (int mb = 0; mb < 4; mb++) {
                int r  = wm + mb * 16 + (lane & 15);
                int cb = kk * 2 + (lane >> 4);          // 16B-chunk index within 8
                ldsm4(af[mb], a_s + (uint32_t)(r * 128) + (uint32_t)((cb ^ (r & 7)) << 4));
            }
            #pragma unroll
            for (int nb = 0; nb < 4; nb++) {
                int l15 = lane & 15;
                int r   = wn + nb * 8 + (l15 & 7);
                int cb  = kk * 2 + (l15 >> 3);
                ldsm2(bf[nb], b_s + (uint32_t)(r * 128) + (uint32_t)((cb ^ (r & 7)) << 4));
            }
            #pragma unroll
            for (int mb = 0; mb < 4; mb++)
                #pragma unroll
                for (int nb = 0; nb < 4; nb++)
                    mma16816(acc[mb][nb], af[mb], bf[nb][0], bf[nb][1]);
        }
    }

    // epilogue
    const int row0 = mt * 128 + wm;
    const int col0 = blockIdx.x * 128 + wn;
    #pragma unroll
    for (int mb = 0; mb < 4; mb++) {
        #pragma unroll
        for (int nb = 0; nb < 4; nb++) {
            int r = row0 + mb * 16 + (lane >> 2);
            int c = col0 + nb * 8 + (lane & 3) * 2;
            float* a = acc[mb][nb];
            if (MODE == 0) {
                *(__half2*)(g_t3 + (size_t)r       * HP + c) = __floats2half2_rn(a[0], a[1]);
                *(__half2*)(g_t3 + (size_t)(r + 8) * HP + c) = __floats2half2_rn(a[2], a[3]);
            } else if (MODE == 1) {
                float2 t0 = __half22float2(*(__half2*)(g_t3 + (size_t)r       * HP + c));
                float2 t1 = __half22float2(*(__half2*)(g_t3 + (size_t)(r + 8) * HP + c));
                float s0 = a[0] / (1.f + __expf(-a[0]));
                float s1 = a[1] / (1.f + __expf(-a[1]));
                float s2 = a[2] / (1.f + __expf(-a[2]));
                float s3 = a[3] / (1.f + __expf(-a[3]));
                *(__half2*)(g_h + (size_t)r       * HP + c) = __floats2half2_rn(s0 * t0.x, s1 * t0.y);
                *(__half2*)(g_h + (size_t)(r + 8) * HP + c) = __floats2half2_rn(s2 * t1.x, s3 * t1.y);
            } else {
                *(float2*)(g_yrows + (size_t)r       * DD + c) = make_float2(a[0], a[1]);
                *(float2*)(g_yrows + (size_t)(r + 8) * DD + c) = make_float2(a[2], a[3]);
            }
        }
    }
}

// -------------------- combine (deterministic gather) --------------------
__global__ void __launch_bounds__(256) moe_combine(float* __restrict__ out) {
    const int t = blockIdx.x;
    const int i = threadIdx.x * 4;
    int   r0 = g_rowof[2*t],  r1 = g_rowof[2*t+1];
    float w0 = g_gws [2*t],  w1 = g_gws [2*t+1];
    float4 a = *(const float4*)(g_yrows + (size_t)r0 * DD + i);
    float4 b = *(const float4*)(g_yrows + (size_t)r1 * DD + i);
    float4 o;
    o.x = w0 * a.x + w1 * b.x;
    o.y = w0 * a.y + w1 * b.y;
    o.z = w0 * a.z + w1 * b.z;
    o.w = w0 * a.w + w1 * b.w;
    *(float4*)(out + (size_t)t * DD + i) = o;
}

// -------------------- launch --------------------
extern "C" void kernel_launch(void* const* d_in, const int* in_sizes, int n_in,
                              void* d_out, int out_size) {
    (void)in_sizes; (void)n_in; (void)out_size;
    const float* x  = (const float*)d_in[0];
    const float* gw = (const float*)d_in[1];
    const float* w1 = (const float*)d_in[2];
    const float* w2 = (const float*)d_in[3];
    const float* w3 = (const float*)d_in[4];
    float* out = (float*)d_out;

    const int smem = 3 * 2 * 16384;  // 96 KB: 3 stages x (16KB A + 16KB B)
    cudaFuncSetAttribute(moe_gemm<0>, cudaFuncAttributeMaxDynamicSharedMemorySize, smem);
    cudaFuncSetAttribute(moe_gemm<1>, cudaFuncAttributeMaxDynamicSharedMemorySize, smem);
    cudaFuncSetAttribute(moe_gemm<2>, cudaFuncAttributeMaxDynamicSharedMemorySize, smem);

    moe_init<<<1, 32>>>();
    moe_router<<<TT / 8, 256>>>(x, gw);
    moe_segplan<<<1, 1>>>();
    moe_build_perm<<<TT / 256, 256>>>();
    moe_gather<<<MMAX, 256>>>(x);
    moe_conv_w13<<<(EE * HP * DD) / 256, 256>>>(w1, w3);
    moe_conv_w2 <<<(EE * DD * HP) / 256, 256>>>(w2);

    moe_gemm<0><<<dim3(HP / 128, MT_MAX), 256, smem>>>();
    moe_gemm<1><<<dim3(HP / 128, MT_MAX), 256, smem>>>();
    moe_gemm<2><<<dim3(DD / 128, MT_MAX), 256, smem>>>();

    moe_combine<<<TT, 256>>>(out);
}

// round 15
// speedup vs baseline: 1.0014x; 1.0009x over previous
#include <cuda_runtime.h>
#include <cuda_fp16.h>
#include <stdint.h>

// Problem constants
#define TT   16384          // tokens = B*S
#define DD   1024           // model dim
#define EE   8              // experts
#define HH   2752           // ffn hidden
#define HP   2816           // hidden padded to multiple of 128
#define MMAX 33792          // 264*128 >= 32768 + 8*127 worst-case padded rows
#define MT_MAX 264

// -------------------- device scratch (no cudaMalloc allowed) --------------------
__device__ __half g_xg [(size_t)MMAX * DD];       // gathered tokens, fp16, segmented
__device__ __half g_w1h[(size_t)EE * HP * DD];    // w1 fp16 [e][HP][D], pad rows zero
__device__ __half g_w3h[(size_t)EE * HP * DD];    // w3 fp16
__device__ __half g_w2h[(size_t)EE * DD * HP];    // w2 fp16 [e][D][HP], pad cols zero
__device__ __half g_t3 [(size_t)MMAX * HP];       // X @ W3^T
__device__ __half g_h  [(size_t)MMAX * HP];       // silu(X@W1^T) * t3
__device__ float  g_yrows[(size_t)MMAX * DD];     // per-row FFN output (fp32)
__device__ int    g_eids [TT * 2];
__device__ float  g_gws  [TT * 2];
__device__ int    g_rowof[TT * 2];
__device__ int    g_perm [MMAX];
__device__ int    g_counts[EE];
__device__ int    g_cursor[EE];
__device__ int    g_segstart[EE + 1];
__device__ int    g_mtile_e[MT_MAX];
__device__ int    g_nmtiles;

// -------------------- asm helpers --------------------
__device__ __forceinline__ void ldsm4(uint32_t* r, uint32_t a) {
    asm volatile("ldmatrix.sync.aligned.m8n8.x4.shared.b16 {%0,%1,%2,%3}, [%4];"
                 : "=r"(r[0]), "=r"(r[1]), "=r"(r[2]), "=r"(r[3]) : "r"(a));
}
__device__ __forceinline__ void ldsm2(uint32_t* r, uint32_t a) {
    asm volatile("ldmatrix.sync.aligned.m8n8.x2.shared.b16 {%0,%1}, [%2];"
                 : "=r"(r[0]), "=r"(r[1]) : "r"(a));
}
__device__ __forceinline__ void mma16816(float* c, const uint32_t* a, uint32_t b0, uint32_t b1) {
    asm volatile("mma.sync.aligned.m16n8k16.row.col.f32.f16.f16.f32 "
                 "{%0,%1,%2,%3}, {%4,%5,%6,%7}, {%8,%9}, {%0,%1,%2,%3};"
                 : "+f"(c[0]), "+f"(c[1]), "+f"(c[2]), "+f"(c[3])
                 : "r"(a[0]), "r"(a[1]), "r"(a[2]), "r"(a[3]), "r"(b0), "r"(b1));
}
__device__ __forceinline__ void cp16(uint32_t s, const void* g) {
    asm volatile("cp.async.cg.shared.global [%0], [%1], 16;" :: "r"(s), "l"(g));
}

// -------------------- routing --------------------
__global__ void moe_init() { if (threadIdx.x < EE) g_counts[threadIdx.x] = 0; }

__global__ void __launch_bounds__(256) moe_router(const float* __restrict__ x,
                                                  const float* __restrict__ gw) {
    __shared__ float sgw[EE * DD];
    for (int i = threadIdx.x; i < EE * DD; i += 256) sgw[i] = gw[i];
    __syncthreads();
    const int t    = blockIdx.x * 8 + (threadIdx.x >> 5);
    const int lane = threadIdx.x & 31;
    const float* xr = x + (size_t)t * DD;
    float acc[EE];
    #pragma unroll
    for (int e = 0; e < EE; e++) acc[e] = 0.f;
    for (int d = lane; d < DD; d += 32) {
        float xv = xr[d];
        #pragma unroll
        for (int e = 0; e < EE; e++) acc[e] += xv * sgw[e * DD + d];
    }
    #pragma unroll
    for (int e = 0; e < EE; e++) {
        #pragma unroll
        for (int o = 16; o > 0; o >>= 1) acc[e] += __shfl_xor_sync(0xffffffffu, acc[e], o);
    }
    if (lane == 0) {
        float m = acc[0];
        #pragma unroll
        for (int e = 1; e < EE; e++) m = fmaxf(m, acc[e]);
        float p[EE];
        #pragma unroll
        for (int e = 0; e < EE; e++) p[e] = __expf(acc[e] - m);
        int i0 = 0; float b0 = p[0];
        #pragma unroll
        for (int e = 1; e < EE; e++) if (p[e] > b0) { b0 = p[e]; i0 = e; }  // ties -> lower idx
        int i1 = (i0 == 0) ? 1 : 0; float b1 = p[i1];
        #pragma unroll
        for (int e = 0; e < EE; e++) if (e != i0 && p[e] > b1) { b1 = p[e]; i1 = e; }
        // softmax denom cancels in top-2 renormalization
        float inv = 1.f / (b0 + b1);
        g_eids[2*t]   = i0;       g_eids[2*t+1] = i1;
        g_gws [2*t]   = b0 * inv; g_gws [2*t+1] = b1 * inv;
        atomicAdd(&g_counts[i0], 1);
        atomicAdd(&g_counts[i1], 1);
    }
}

__global__ void moe_segplan() {
    int off = 0;
    for (int e = 0; e < EE; e++) {
        g_segstart[e] = off;
        g_cursor[e]   = 0;
        int mt = (g_counts[e] + 127) >> 7;
        for (int i = 0; i < mt; i++) g_mtile_e[(off >> 7) + i] = e;
        off += mt << 7;
    }
    g_segstart[EE] = off;
    g_nmtiles = off >> 7;
}

__global__ void __launch_bounds__(256) moe_build_perm() {
    int t = blockIdx.x * 256 + threadIdx.x;
    #pragma unroll
    for (int k = 0; k < 2; k++) {
        int e   = g_eids[2*t + k];
        int pos = atomicAdd(&g_cursor[e], 1);
        int row = g_segstart[e] + pos;
        g_perm[row]     = t;
        g_rowof[2*t+k]  = row;
    }
}

// gather tokens into segmented fp16 layout; pad rows zeroed
__global__ void __launch_bounds__(256) moe_gather(const float* __restrict__ x) {
    const int r = blockIdx.x;
    int e = 0;
    #pragma unroll
    for (int q = 0; q < EE - 1; q++) if (r >= g_segstart[q + 1]) e = q + 1;
    const bool valid = (r - g_segstart[e]) < g_counts[e];
    const int i = threadIdx.x * 4;
    float4 v = make_float4(0.f, 0.f, 0.f, 0.f);
    if (valid) {
        int t = g_perm[r];
        v = *(const float4*)(x + (size_t)t * DD + i);
    }
    __half2* dst = (__half2*)(g_xg + (size_t)r * DD + i);
    dst[0] = __floats2half2_rn(v.x, v.y);
    dst[1] = __floats2half2_rn(v.z, v.w);
}

// -------------------- weight conversion fp32 -> fp16 (padded) --------------------
__global__ void __launch_bounds__(256) moe_conv_w13(const float* __restrict__ w1,
                                                    const float* __restrict__ w3) {
    size_t i = (size_t)blockIdx.x * 256 + threadIdx.x;   // over EE*HP*DD
    int d = (int)(i & (DD - 1));
    size_t rem = i >> 10;
    int r = (int)(rem % HP);
    int e = (int)(rem / HP);
    __half v1 = __float2half_rn(0.f), v3 = __float2half_rn(0.f);
    if (r < HH) {
        size_t src = ((size_t)e * HH + r) * DD + d;
        v1 = __float2half_rn(w1[src]);
        v3 = __float2half_rn(w3[src]);
    }
    g_w1h[i] = v1; g_w3h[i] = v3;
}

__global__ void __launch_bounds__(256) moe_conv_w2(const float* __restrict__ w2) {
    size_t i = (size_t)blockIdx.x * 256 + threadIdx.x;   // over EE*DD*HP
    int c = (int)(i % HP);
    size_t rem = i / HP;
    int r = (int)(rem & (DD - 1));
    int e = (int)(rem >> 10);
    __half v = __float2half_rn(0.f);
    if (c < HH) v = __float2half_rn(w2[((size_t)e * DD + r) * HH + c]);
    g_w2h[i] = v;
}

// -------------------- GEMM: C[128x128] = A[128xK] @ B[128xK]^T --------------------
// MODE 0: A=g_xg  B=g_w3h -> g_t3 (fp16)
// MODE 1: A=g_xg  B=g_w1h -> g_h = silu(acc) * g_t3 (fp16)
// MODE 2: A=g_h   B=g_w2h -> g_yrows (fp32)
template<int MODE>
__global__ void __launch_bounds__(256) moe_gemm() {
    constexpr int K   = (MODE == 2) ? HP : DD;
    constexpr int KIT = K / 64;

    const int mt = blockIdx.y;
    if (mt >= g_nmtiles) return;
    const int e = g_mtile_e[mt];

    const __half* A = (MODE == 2) ? g_h : g_xg;
    const __half* B = (MODE == 0) ? g_w3h + (size_t)e * HP * DD :
                      (MODE == 1) ? g_w1h + (size_t)e * HP * DD :
                                    g_w2h + (size_t)e * DD * HP;

    extern __shared__ char smem_raw[];
    const uint32_t sbase = (uint32_t)__cvta_generic_to_shared(smem_raw);
    const uint32_t sA = sbase, sB = sbase + 3 * 16384;
    const int tid = threadIdx.x;
    const __half* Ag = A + (size_t)mt * 128 * K;
    const __half* Bg = B + (size_t)blockIdx.x * 128 * K;

    auto load_stage = [&](int st, int kt) {
        uint32_t da = sA + st * 16384, db = sB + st * 16384;
        const __half* ga = Ag + kt * 64;
        const __half* gb = Bg + kt * 64;
        #pragma unroll
        for (int i = 0; i < 4; i++) {
            int idx = i * 256 + tid;          // 1024 chunks of 16B = 128 rows x 8 chunks
            int r = idx >> 3, c = idx & 7;
            uint32_t so = (uint32_t)(r * 128) + (uint32_t)((c ^ (r & 7)) << 4);
            size_t go = (size_t)r * K + c * 8;
            cp16(da + so, ga + go);
            cp16(db + so, gb + go);
        }
    };
    load_stage(0, 0); asm volatile("cp.async.commit_group;" ::: "memory");
    load_stage(1, 1); asm volatile("cp.async.commit_group;" ::: "memory");

    const int lane = tid & 31, wid = tid >> 5;
    const int wm = (wid >> 2) * 64, wn = (wid & 3) * 32;

    float acc[4][4][4];
    #pragma unroll
    for (int a = 0; a < 4; a++)
        #pragma unroll
        for (int b = 0; b < 4; b++)
            #pragma unroll
            for (int q = 0; q < 4; q++) acc[a][b][q] = 0.f;

    #pragma unroll 1
    for (int kt = 0; kt < KIT; kt++) {
        asm volatile("cp.async.wait_group 1;" ::: "memory");
        __syncthreads();
        if (kt + 2 < KIT) load_stage((kt + 2) % 3, kt + 2);
        asm volatile("cp.async.commit_group;" ::: "memory");
        const uint32_t a_s = sA + (kt % 3) * 16384;
        const uint32_t b_s = sB + (kt % 3) * 16384;
        #pragma unroll
        for (int kk = 0; kk < 4; kk++) {
            uint32_t af[4][4], bf[4][2];
            #pragma unroll
            for (int mb = 0; mb < 4; mb++) {
                int r  = wm + mb * 16 + (lane & 15);
                int cb = kk * 2 + (lane >> 4);          // 16B-chunk index within 8
                ldsm4(af[mb], a_s + (uint32_t)(r * 128) + (uint32_t)((cb ^ (r & 7)) << 4));
            }
            #pragma unroll
            for (int nb = 0; nb < 4; nb++) {
                int l15 = lane & 15;
                int r   = wn + nb * 8 + (l15 & 7);
                int cb  = kk * 2 + (l15 >> 3);
                ldsm2(bf[nb], b_s + (uint32_t)(r * 128) + (uint32_t)((cb ^ (r & 7)) << 4));
            }
            #pragma unroll
            for (int mb = 0; mb < 4; mb++)
                #pragma unroll
                for (int nb = 0; nb < 4; nb++)
                    mma16816(acc[mb][nb], af[mb], bf[nb][0], bf[nb][1]);
        }
    }

    // epilogue
    const int row0 = mt * 128 + wm;
    const int col0 = blockIdx.x * 128 + wn;
    #pragma unroll
    for (int mb = 0; mb < 4; mb++) {
        #pragma unroll
        for (int nb = 0; nb < 4; nb++) {
            int r = row0 + mb * 16 + (lane >> 2);
            int c = col0 + nb * 8 + (lane & 3) * 2;
            float* a = acc[mb][nb];
            if (MODE == 0) {
                *(__half2*)(g_t3 + (size_t)r       * HP + c) = __floats2half2_rn(a[0], a[1]);
                *(__half2*)(g_t3 + (size_t)(r + 8) * HP + c) = __floats2half2_rn(a[2], a[3]);
            } else if (MODE == 1) {
                float2 t0 = __half22float2(*(__half2*)(g_t3 + (size_t)r       * HP + c));
                float2 t1 = __half22float2(*(__half2*)(g_t3 + (size_t)(r + 8) * HP + c));
                float s0 = a[0] / (1.f + __expf(-a[0]));
                float s1 = a[1] / (1.f + __expf(-a[1]));
                float s2 = a[2] / (1.f + __expf(-a[2]));
                float s3 = a[3] / (1.f + __expf(-a[3]));
                *(__half2*)(g_h + (size_t)r       * HP + c) = __floats2half2_rn(s0 * t0.x, s1 * t0.y);
                *(__half2*)(g_h + (size_t)(r + 8) * HP + c) = __floats2half2_rn(s2 * t1.x, s3 * t1.y);
            } else {
                *(float2*)(g_yrows + (size_t)r       * DD + c) = make_float2(a[0], a[1]);
                *(float2*)(g_yrows + (size_t)(r + 8) * DD + c) = make_float2(a[2], a[3]);
            }
        }
    }
}

// -------------------- combine (deterministic gather) --------------------
__global__ void __launch_bounds__(256) moe_combine(float* __restrict__ out) {
    const int t = blockIdx.x;
    const int i = threadIdx.x * 4;
    int   r0 = g_rowof[2*t],  r1 = g_rowof[2*t+1];
    float w0 = g_gws [2*t],  w1 = g_gws [2*t+1];
    float4 a = *(const float4*)(g_yrows + (size_t)r0 * DD + i);
    float4 b = *(const float4*)(g_yrows + (size_t)r1 * DD + i);
    float4 o;
    o.x = w0 * a.x + w1 * b.x;
    o.y = w0 * a.y + w1 * b.y;
    o.z = w0 * a.z + w1 * b.z;
    o.w = w0 * a.w + w1 * b.w;
    *(float4*)(out + (size_t)t * DD + i) = o;
}

// -------------------- launch --------------------
extern "C" void kernel_launch(void* const* d_in, const int* in_sizes, int n_in,
                              void* d_out, int out_size) {
    (void)in_sizes; (void)n_in; (void)out_size;
    const float* x  = (const float*)d_in[0];
    const float* gw = (const float*)d_in[1];
    const float* w1 = (const float*)d_in[2];
    const float* w2 = (const float*)d_in[3];
    const float* w3 = (const float*)d_in[4];
    float* out = (float*)d_out;

    const int smem = 3 * 2 * 16384;  // 96 KB: 3 stages x (16KB A + 16KB B)
    cudaFuncSetAttribute(moe_gemm<0>, cudaFuncAttributeMaxDynamicSharedMemorySize, smem);
    cudaFuncSetAttribute(moe_gemm<1>, cudaFuncAttributeMaxDynamicSharedMemorySize, smem);
    cudaFuncSetAttribute(moe_gemm<2>, cudaFuncAttributeMaxDynamicSharedMemorySize, smem);

    moe_init<<<1, 32>>>();
    moe_router<<<TT / 8, 256>>>(x, gw);
    moe_segplan<<<1, 1>>>();
    moe_build_perm<<<TT / 256, 256>>>();
    moe_gather<<<MMAX, 256>>>(x);
    moe_conv_w13<<<(EE * HP * DD) / 256, 256>>>(w1, w3);
    moe_conv_w2 <<<(EE * DD * HP) / 256, 256>>>(w2);

    moe_gemm<0><<<dim3(HP / 128, MT_MAX), 256, smem>>>();
    moe_gemm<1><<<dim3(HP / 128, MT_MAX), 256, smem>>>();
    moe_gemm<2><<<dim3(DD / 128, MT_MAX), 256, smem>>>();

    moe_combine<<<TT, 256>>>(out);
}

// round 17
// speedup vs baseline: 1.0155x; 1.0142x over previous
#include <cuda_runtime.h>
#include <cuda_fp16.h>
#include <stdint.h>

// Problem constants
#define TT   16384          // tokens = B*S
#define DD   1024           // model dim
#define EE   8              // experts
#define HH   2752           // ffn hidden
#define HP   2816           // hidden padded to multiple of 128
#define MMAX 33792          // 264*128 >= 32768 + 8*127 worst-case padded rows
#define MT_MAX 264

// -------------------- device scratch (no cudaMalloc allowed) --------------------
__device__ __half g_xg [(size_t)MMAX * DD];       // gathered tokens, fp16, segmented
__device__ __half g_w1h[(size_t)EE * HP * DD];    // w1 fp16 [e][HP][D], pad rows zero
__device__ __half g_w3h[(size_t)EE * HP * DD];    // w3 fp16
__device__ __half g_w2h[(size_t)EE * DD * HP];    // w2 fp16 [e][D][HP], pad cols zero
__device__ __half g_h  [(size_t)MMAX * HP];       // silu(X@W1^T) * (X@W3^T)
__device__ float  g_yrows[(size_t)MMAX * DD];     // per-row FFN output (fp32)
__device__ int    g_eids [TT * 2];
__device__ float  g_gws  [TT * 2];
__device__ int    g_rowof[TT * 2];
__device__ int    g_perm [MMAX];
__device__ int    g_counts[EE];
__device__ int    g_cursor[EE];
__device__ int    g_segstart[EE + 1];
__device__ int    g_mtile_e[MT_MAX];
__device__ int    g_nmtiles;

// -------------------- asm helpers --------------------
__device__ __forceinline__ void ldsm4(uint32_t* r, uint32_t a) {
    asm volatile("ldmatrix.sync.aligned.m8n8.x4.shared.b16 {%0,%1,%2,%3}, [%4];"
                 : "=r"(r[0]), "=r"(r[1]), "=r"(r[2]), "=r"(r[3]) : "r"(a));
}
__device__ __forceinline__ void mma16816(float* c, const uint32_t* a, uint32_t b0, uint32_t b1) {
    asm volatile("mma.sync.aligned.m16n8k16.row.col.f32.f16.f16.f32 "
                 "{%0,%1,%2,%3}, {%4,%5,%6,%7}, {%8,%9}, {%0,%1,%2,%3};"
                 : "+f"(c[0]), "+f"(c[1]), "+f"(c[2]), "+f"(c[3])
                 : "r"(a[0]), "r"(a[1]), "r"(a[2]), "r"(a[3]), "r"(b0), "r"(b1));
}
__device__ __forceinline__ void cp16(uint32_t s, const void* g) {
    asm volatile("cp.async.cg.shared.global [%0], [%1], 16;" :: "r"(s), "l"(g));
}

// -------------------- routing --------------------
__global__ void moe_init() { if (threadIdx.x < EE) g_counts[threadIdx.x] = 0; }

__global__ void __launch_bounds__(256) moe_router(const float* __restrict__ x,
                                                  const float* __restrict__ gw) {
    __shared__ float sgw[EE * DD];
    for (int i = threadIdx.x; i < EE * DD; i += 256) sgw[i] = gw[i];
    __syncthreads();
    const int t    = blockIdx.x * 8 + (threadIdx.x >> 5);
    const int lane = threadIdx.x & 31;
    const float* xr = x + (size_t)t * DD;
    float acc[EE];
    #pragma unroll
    for (int e = 0; e < EE; e++) acc[e] = 0.f;
    for (int d = lane; d < DD; d += 32) {
        float xv = xr[d];
        #pragma unroll
        for (int e = 0; e < EE; e++) acc[e] += xv * sgw[e * DD + d];
    }
    #pragma unroll
    for (int e = 0; e < EE; e++) {
        #pragma unroll
        for (int o = 16; o > 0; o >>= 1) acc[e] += __shfl_xor_sync(0xffffffffu, acc[e], o);
    }
    if (lane == 0) {
        float m = acc[0];
        #pragma unroll
        for (int e = 1; e < EE; e++) m = fmaxf(m, acc[e]);
        float p[EE];
        #pragma unroll
        for (int e = 0; e < EE; e++) p[e] = __expf(acc[e] - m);
        int i0 = 0; float b0 = p[0];
        #pragma unroll
        for (int e = 1; e < EE; e++) if (p[e] > b0) { b0 = p[e]; i0 = e; }  // ties -> lower idx
        int i1 = (i0 == 0) ? 1 : 0; float b1 = p[i1];
        #pragma unroll
        for (int e = 0; e < EE; e++) if (e != i0 && p[e] > b1) { b1 = p[e]; i1 = e; }
        float inv = 1.f / (b0 + b1);  // softmax denom cancels in top-2 renorm
        g_eids[2*t]   = i0;       g_eids[2*t+1] = i1;
        g_gws [2*t]   = b0 * inv; g_gws [2*t+1] = b1 * inv;
        atomicAdd(&g_counts[i0], 1);
        atomicAdd(&g_counts[i1], 1);
    }
}

__global__ void moe_segplan() {
    int off = 0;
    for (int e = 0; e < EE; e++) {
        g_segstart[e] = off;
        g_cursor[e]   = 0;
        int mt = (g_counts[e] + 127) >> 7;
        for (int i = 0; i < mt; i++) g_mtile_e[(off >> 7) + i] = e;
        off += mt << 7;
    }
    g_segstart[EE] = off;
    g_nmtiles = off >> 7;
}

__global__ void __launch_bounds__(256) moe_build_perm() {
    int t = blockIdx.x * 256 + threadIdx.x;
    #pragma unroll
    for (int k = 0; k < 2; k++) {
        int e   = g_eids[2*t + k];
        int pos = atomicAdd(&g_cursor[e], 1);
        int row = g_segstart[e] + pos;
        g_perm[row]     = t;
        g_rowof[2*t+k]  = row;
    }
}

// gather tokens into segmented fp16 layout; pad rows zeroed
__global__ void __launch_bounds__(256) moe_gather(const float* __restrict__ x) {
    const int r = blockIdx.x;
    int e = 0;
    #pragma unroll
    for (int q = 0; q < EE - 1; q++) if (r >= g_segstart[q + 1]) e = q + 1;
    const bool valid = (r - g_segstart[e]) < g_counts[e];
    const int i = threadIdx.x * 4;
    float4 v = make_float4(0.f, 0.f, 0.f, 0.f);
    if (valid) {
        int t = g_perm[r];
        v = *(const float4*)(x + (size_t)t * DD + i);
    }
    __half2* dst = (__half2*)(g_xg + (size_t)r * DD + i);
    dst[0] = __floats2half2_rn(v.x, v.y);
    dst[1] = __floats2half2_rn(v.z, v.w);
}

// -------------------- weight conversion fp32 -> fp16 (padded) --------------------
__global__ void __launch_bounds__(256) moe_conv_w13(const float* __restrict__ w1,
                                                    const float* __restrict__ w3) {
    size_t i = (size_t)blockIdx.x * 256 + threadIdx.x;   // over EE*HP*DD
    int d = (int)(i & (DD - 1));
    size_t rem = i >> 10;
    int r = (int)(rem % HP);
    int e = (int)(rem / HP);
    __half v1 = __float2half_rn(0.f), v3 = __float2half_rn(0.f);
    if (r < HH) {
        size_t src = ((size_t)e * HH + r) * DD + d;
        v1 = __float2half_rn(w1[src]);
        v3 = __float2half_rn(w3[src]);
    }
    g_w1h[i] = v1; g_w3h[i] = v3;
}

__global__ void __launch_bounds__(256) moe_conv_w2(const float* __restrict__ w2) {
    size_t i = (size_t)blockIdx.x * 256 + threadIdx.x;   // over EE*DD*HP
    int c = (int)(i % HP);
    size_t rem = i / HP;
    int r = (int)(rem & (DD - 1));
    int e = (int)(rem >> 10);
    __half v = __float2half_rn(0.f);
    if (c < HH) v = __float2half_rn(w2[((size_t)e * DD + r) * HH + c]);
    g_w2h[i] = v;
}

// -------------------- fused GEMM13: acc1 = X@W1^T, acc3 = X@W3^T --------------------
// CTA tile 128(m) x 128(n), K = DD = 1024, 4-stage cp.async pipeline.
// Epilogue: g_h = silu(acc1) * acc3 (fp16). No t3 intermediate.
__global__ void __launch_bounds__(256) moe_gemm13() {
    constexpr int K   = DD;
    constexpr int KIT = K / 64;           // 16
    constexpr int ST  = 4;
    constexpr int STAGE = 3 * 16384;      // A + B1 + B3

    const int mt = blockIdx.y;
    if (mt >= g_nmtiles) return;
    const int e  = g_mtile_e[mt];
    const int nt = blockIdx.x;

    extern __shared__ char smem_raw[];
    const uint32_t sbase = (uint32_t)__cvta_generic_to_shared(smem_raw);
    const int tid = threadIdx.x;
    const __half* Ag  = g_xg  + (size_t)mt * 128 * K;
    const __half* B1g = g_w1h + (size_t)e * HP * DD + (size_t)nt * 128 * K;
    const __half* B3g = g_w3h + (size_t)e * HP * DD + (size_t)nt * 128 * K;

    auto load_stage = [&](int st, int kt) {
        uint32_t base = sbase + (uint32_t)st * STAGE;
        const __half* ga = Ag  + kt * 64;
        const __half* g1 = B1g + kt * 64;
        const __half* g3 = B3g + kt * 64;
        #pragma unroll
        for (int i = 0; i < 4; i++) {
            int idx = i * 256 + tid;          // 1024 chunks of 16B = 128 rows x 8 chunks
            int r = idx >> 3, c = idx & 7;
            uint32_t so = (uint32_t)(r * 128) + (uint32_t)((c ^ (r & 7)) << 4);
            size_t go = (size_t)r * K + c * 8;
            cp16(base + so,         ga + go);
            cp16(base + 16384 + so, g1 + go);
            cp16(base + 32768 + so, g3 + go);
        }
    };
    load_stage(0, 0); asm volatile("cp.async.commit_group;" ::: "memory");
    load_stage(1, 1); asm volatile("cp.async.commit_group;" ::: "memory");
    load_stage(2, 2); asm volatile("cp.async.commit_group;" ::: "memory");

    const int lane = tid & 31, wid = tid >> 5;
    const int wm = (wid >> 2) * 64, wn = (wid & 3) * 32;

    float acc1[4][4][4], acc3[4][4][4];
    #pragma unroll
    for (int a = 0; a < 4; a++)
        #pragma unroll
        for (int b = 0; b < 4; b++)
            #pragma unroll
            for (int q = 0; q < 4; q++) { acc1[a][b][q] = 0.f; acc3[a][b][q] = 0.f; }

    #pragma unroll 1
    for (int kt = 0; kt < KIT; kt++) {
        asm volatile("cp.async.wait_group 2;" ::: "memory");   // stage kt resident
        __syncthreads();
        if (kt + 3 < KIT) load_stage((kt + 3) % ST, kt + 3);
        asm volatile("cp.async.commit_group;" ::: "memory");
        const uint32_t a_s  = sbase + (uint32_t)(kt % ST) * STAGE;
        const uint32_t b1_s = a_s + 16384;
        const uint32_t b3_s = a_s + 32768;
        #pragma unroll
        for (int kk = 0; kk < 4; kk++) {
            uint32_t af[4][4], bf1[2][4], bf3[2][4];
            // A fragments: 4 x ldsm4 (16x16 each)
            #pragma unroll
            for (int mb = 0; mb < 4; mb++) {
                int r  = wm + mb * 16 + (lane & 15);
                int cb = kk * 2 + (lane >> 4);
                ldsm4(af[mb], a_s + (uint32_t)(r * 128) + (uint32_t)((cb ^ (r & 7)) << 4));
            }
            // B fragments: ldsm4 packs two n-blocks x two k-halves
            // lane group g = lane>>3: matrix g -> (nb = nbp*2 + (g>>1), khalf = g&1)
            #pragma unroll
            for (int nbp = 0; nbp < 2; nbp++) {
                int g  = lane >> 3;
                int r  = wn + nbp * 16 + (g >> 1) * 8 + (lane & 7);
                int cb = kk * 2 + (g & 1);
                uint32_t addr = (uint32_t)(r * 128) + (uint32_t)((cb ^ (r & 7)) << 4);
                ldsm4(bf1[nbp], b1_s + addr);
                ldsm4(bf3[nbp], b3_s + addr);
            }
            #pragma unroll
            for (int mb = 0; mb < 4; mb++) {
                #pragma unroll
                for (int nbp = 0; nbp < 2; nbp++) {
                    mma16816(acc1[mb][nbp*2+0], af[mb], bf1[nbp][0], bf1[nbp][1]);
                    mma16816(acc1[mb][nbp*2+1], af[mb], bf1[nbp][2], bf1[nbp][3]);
                    mma16816(acc3[mb][nbp*2+0], af[mb], bf3[nbp][0], bf3[nbp][1]);
                    mma16816(acc3[mb][nbp*2+1], af[mb], bf3[nbp][2], bf3[nbp][3]);
                }
            }
        }
    }

    // epilogue: h = silu(acc1) * acc3, fp16
    const int row0 = mt * 128 + wm;
    const int col0 = nt * 128 + wn;
    #pragma unroll
    for (int mb = 0; mb < 4; mb++) {
        #pragma unroll
        for (int nb = 0; nb < 4; nb++) {
            int r = row0 + mb * 16 + (lane >> 2);
            int c = col0 + nb * 8 + (lane & 3) * 2;
            float* a1 = acc1[mb][nb];
            float* a3 = acc3[mb][nb];
            float h0 = a1[0] / (1.f + __expf(-a1[0])) * a3[0];
            float h1 = a1[1] / (1.f + __expf(-a1[1])) * a3[1];
            float h2 = a1[2] / (1.f + __expf(-a1[2])) * a3[2];
            float h3 = a1[3] / (1.f + __expf(-a1[3])) * a3[3];
            *(__half2*)(g_h + (size_t)r       * HP + c) = __floats2half2_rn(h0, h1);
            *(__half2*)(g_h + (size_t)(r + 8) * HP + c) = __floats2half2_rn(h2, h3);
        }
    }
}

// -------------------- GEMM2: g_yrows = H @ W2^T (fp32 out) --------------------
// Proven R15 structure: 128x128 tile, 3-stage pipeline, K = HP = 2816.
__global__ void __launch_bounds__(256) moe_gemm2() {
    constexpr int K   = HP;
    constexpr int KIT = K / 64;

    const int mt = blockIdx.y;
    if (mt >= g_nmtiles) return;
    const int e = g_mtile_e[mt];

    extern __shared__ char smem_raw[];
    const uint32_t sbase = (uint32_t)__cvta_generic_to_shared(smem_raw);
    const uint32_t sA = sbase, sB = sbase + 3 * 16384;
    const int tid = threadIdx.x;
    const __half* Ag = g_h + (size_t)mt * 128 * K;
    const __half* Bg = g_w2h + (size_t)e * DD * HP + (size_t)blockIdx.x * 128 * K;

    auto load_stage = [&](int st, int kt) {
        uint32_t da = sA + st * 16384, db = sB + st * 16384;
        const __half* ga = Ag + kt * 64;
        const __half* gb = Bg + kt * 64;
        #pragma unroll
        for (int i = 0; i < 4; i++) {
            int idx = i * 256 + tid;
            int r = idx >> 3, c = idx & 7;
            uint32_t so = (uint32_t)(r * 128) + (uint32_t)((c ^ (r & 7)) << 4);
            size_t go = (size_t)r * K + c * 8;
            cp16(da + so, ga + go);
            cp16(db + so, gb + go);
        }
    };
    load_stage(0, 0); asm volatile("cp.async.commit_group;" ::: "memory");
    load_stage(1, 1); asm volatile("cp.async.commit_group;" ::: "memory");

    const int lane = tid & 31, wid = tid >> 5;
    const int wm = (wid >> 2) * 64, wn = (wid & 3) * 32;

    float acc[4][4][4];
    #pragma unroll
    for (int a = 0; a < 4; a++)
        #pragma unroll
        for (int b = 0; b < 4; b++)
            #pragma unroll
            for (int q = 0; q < 4; q++) acc[a][b][q] = 0.f;

    #pragma unroll 1
    for (int kt = 0; kt < KIT; kt++) {
        asm volatile("cp.async.wait_group 1;" ::: "memory");
        __syncthreads();
        if (kt + 2 < KIT) load_stage((kt + 2) % 3, kt + 2);
        asm volatile("cp.async.commit_group;" ::: "memory");
        const uint32_t a_s = sA + (kt % 3) * 16384;
        const uint32_t b_s = sB + (kt % 3) * 16384;
        #pragma unroll
        for (int kk = 0; kk < 4; kk++) {
            uint32_t af[4][4], bf[2][4];
            #pragma unroll
            for (int mb = 0; mb < 4; mb++) {
                int r  = wm + mb * 16 + (lane & 15);
                int cb = kk * 2 + (lane >> 4);
                ldsm4(af[mb], a_s + (uint32_t)(r * 128) + (uint32_t)((cb ^ (r & 7)) << 4));
            }
            #pragma unroll
            for (int nbp = 0; nbp < 2; nbp++) {
                int g  = lane >> 3;
                int r  = wn + nbp * 16 + (g >> 1) * 8 + (lane & 7);
                int cb = kk * 2 + (g & 1);
                ldsm4(bf[nbp], b_s + (uint32_t)(r * 128) + (uint32_t)((cb ^ (r & 7)) << 4));
            }
            #pragma unroll
            for (int mb = 0; mb < 4; mb++) {
                #pragma unroll
                for (int nbp = 0; nbp < 2; nbp++) {
                    mma16816(acc[mb][nbp*2+0], af[mb], bf[nbp][0], bf[nbp][1]);
                    mma16816(acc[mb][nbp*2+1], af[mb], bf[nbp][2], bf[nbp][3]);
                }
            }
        }
    }

    const int row0 = mt * 128 + wm;
    const int col0 = blockIdx.x * 128 + wn;
    #pragma unroll
    for (int mb = 0; mb < 4; mb++) {
        #pragma unroll
        for (int nb = 0; nb < 4; nb++) {
            int r = row0 + mb * 16 + (lane >> 2);
            int c = col0 + nb * 8 + (lane & 3) * 2;
            float* a = acc[mb][nb];
            *(float2*)(g_yrows + (size_t)r       * DD + c) = make_float2(a[0], a[1]);
            *(float2*)(g_yrows + (size_t)(r + 8) * DD + c) = make_float2(a[2], a[3]);
        }
    }
}

// -------------------- combine (deterministic gather) --------------------
__global__ void __launch_bounds__(256) moe_combine(float* __restrict__ out) {
    const int t = blockIdx.x;
    const int i = threadIdx.x * 4;
    int   r0 = g_rowof[2*t],  r1 = g_rowof[2*t+1];
    float w0 = g_gws [2*t],   w1 = g_gws [2*t+1];
    float4 a = *(const float4*)(g_yrows + (size_t)r0 * DD + i);
    float4 b = *(const float4*)(g_yrows + (size_t)r1 * DD + i);
    float4 o;
    o.x = w0 * a.x + w1 * b.x;
    o.y = w0 * a.y + w1 * b.y;
    o.z = w0 * a.z + w1 * b.z;
    o.w = w0 * a.w + w1 * b.w;
    *(float4*)(out + (size_t)t * DD + i) = o;
}

// -------------------- launch --------------------
extern "C" void kernel_launch(void* const* d_in, const int* in_sizes, int n_in,
                              void* d_out, int out_size) {
    (void)in_sizes; (void)n_in; (void)out_size;
    const float* x  = (const float*)d_in[0];
    const float* gw = (const float*)d_in[1];
    const float* w1 = (const float*)d_in[2];
    const float* w2 = (const float*)d_in[3];
    const float* w3 = (const float*)d_in[4];
    float* out = (float*)d_out;

    const int smem13 = 4 * 3 * 16384;  // 196608 B: 4 stages x (A + B1 + B3)
    const int smem2  = 3 * 2 * 16384;  //  98304 B: 3 stages x (A + B)
    cudaFuncSetAttribute(moe_gemm13, cudaFuncAttributeMaxDynamicSharedMemorySize, smem13);
    cudaFuncSetAttribute(moe_gemm2,  cudaFuncAttributeMaxDynamicSharedMemorySize, smem2);

    moe_init<<<1, 32>>>();
    moe_router<<<TT / 8, 256>>>(x, gw);
    moe_segplan<<<1, 1>>>();
    moe_build_perm<<<TT / 256, 256>>>();
    moe_gather<<<MMAX, 256>>>(x);
    moe_conv_w13<<<(EE * HP * DD) / 256, 256>>>(w1, w3);
    moe_conv_w2 <<<(EE * DD * HP) / 256, 256>>>(w2);

    moe_gemm13<<<dim3(HP / 128, MT_MAX), 256, smem13>>>();
    moe_gemm2 <<<dim3(DD / 128, MT_MAX), 256, smem2 >>>();

    moe_combine<<<TT, 256>>>(out);
}